// round 5
// baseline (speedup 1.0000x reference)
#include <cuda_runtime.h>
#include <cuda_fp16.h>
#include <math.h>
#include <stdint.h>

#define B_ 16
#define C_ 512
#define HW_ 4096
#define HEADS_ 8
#define HK_ 64

// ------------------------- scratch (device globals) -------------------------
__device__ __half g_xt[(size_t)B_ * HW_ * C_];   // x transposed fp16; reused as AVt
__device__ __half g_kh[(size_t)B_ * C_ * HW_];   // k fp16 (softmaxed in place)
__device__ __half g_vh[(size_t)B_ * C_ * HW_];   // v fp16
__device__ __half g_qt[(size_t)B_ * HW_ * C_];   // softmaxed q transposed [bh][l][64]
__device__ float  g_ctxf[B_ * HEADS_ * HK_ * HK_]; // fp32 ctx accum [bh][k][v]
__device__ __half g_ctxh[B_ * HEADS_ * HK_ * HK_]; // ctxT [bh][v][k]
__device__ __half g_wc[1536 * 512];              // Wq|Wk|Wv fp16
__device__ __half g_wr[512 * 512];               // Wr fp16
__device__ float g_bcat[1536];

// ------------------------- PTX helpers -------------------------
__device__ __forceinline__ uint32_t smem_u32(const void* p) {
    return (uint32_t)__cvta_generic_to_shared(p);
}
__device__ __forceinline__ void cp16(uint32_t dst, const void* src) {
    asm volatile("cp.async.cg.shared.global [%0], [%1], 16;\n" :: "r"(dst), "l"(src));
}
__device__ __forceinline__ void cp_commit() {
    asm volatile("cp.async.commit_group;\n" ::: "memory");
}
template <int N>
__device__ __forceinline__ void cp_wait() {
    asm volatile("cp.async.wait_group %0;\n" :: "n"(N) : "memory");
}
__device__ __forceinline__ uint32_t sw128(uint32_t off) {
    return off ^ ((off >> 3) & 0x70);
}
__device__ __forceinline__ void ldsm4(uint32_t& r0, uint32_t& r1, uint32_t& r2,
                                      uint32_t& r3, uint32_t addr) {
    asm volatile("ldmatrix.sync.aligned.m8n8.x4.shared.b16 {%0,%1,%2,%3}, [%4];"
                 : "=r"(r0), "=r"(r1), "=r"(r2), "=r"(r3) : "r"(addr));
}
__device__ __forceinline__ void mma16816(float* c, uint32_t a0, uint32_t a1,
                                         uint32_t a2, uint32_t a3,
                                         uint32_t b0, uint32_t b1) {
    asm volatile(
        "mma.sync.aligned.m16n8k16.row.col.f32.f16.f16.f32 "
        "{%0,%1,%2,%3}, {%4,%5,%6,%7}, {%8,%9}, {%0,%1,%2,%3};"
        : "+f"(c[0]), "+f"(c[1]), "+f"(c[2]), "+f"(c[3])
        : "r"(a0), "r"(a1), "r"(a2), "r"(a3), "r"(b0), "r"(b1));
}

// ------------------------- prepass: weight convert/concat -------------------------
__global__ void __launch_bounds__(256) weight_prep(
    const float* __restrict__ Wq, const float* __restrict__ bq,
    const float* __restrict__ Wk, const float* __restrict__ bk,
    const float* __restrict__ Wv, const float* __restrict__ bv,
    const float* __restrict__ Wr)
{
    const int idx = blockIdx.x * 256 + threadIdx.x;   // < 2048*512
    const int m = idx >> 9;
    const int kk = idx & 511;
    if (m < 1536) {
        const float* src = (m < 512) ? Wq : (m < 1024) ? Wk : Wv;
        g_wc[idx] = __float2half(src[(size_t)(m & 511) * 512 + kk]);
    } else {
        g_wr[(size_t)(m - 1536) * 512 + kk] =
            __float2half(Wr[(size_t)(m - 1536) * 512 + kk]);
    }
    if (idx < 1536)
        g_bcat[idx] = (idx < 512) ? bq[idx] : (idx < 1024) ? bk[idx - 512] : bv[idx - 1024];
}

// ------------------------- prepass: transpose + convert x -------------------------
__global__ void __launch_bounds__(256) transpose_cvt(const float* __restrict__ X)
{
    __shared__ float t[32][33];
    const int l0 = blockIdx.x * 32;
    const int c0 = blockIdx.y * 32;
    const int b  = blockIdx.z;
    const int tx = threadIdx.x, ty = threadIdx.y;
    #pragma unroll
    for (int j = 0; j < 4; j++)
        t[ty + j * 8][tx] = X[((size_t)b * C_ + c0 + ty + j * 8) * HW_ + l0 + tx];
    __syncthreads();
    #pragma unroll
    for (int j = 0; j < 4; j++) {
        size_t o = ((size_t)b * HW_ + l0 + ty + j * 8) * C_ + c0 + tx;
        g_xt[o] = __float2half(t[tx][ty + j * 8]);
    }
}

// ------------------------- HMMA fp16 GEMM (projections) -------------------------
// D[m][n] = sum_k A[m][k]*B[n][k] + bias[m]; CTA 128x128, K chunks 64, 3-stage.
// QFUSE: q output tiles (sel==0) get per-head channel-softmax fused + transposed
// write to qt[bh][l][64].
#define GEMM_SMEM_TOTAL 98304

template <bool OUT_HALF, bool QFUSE>
__global__ void __launch_bounds__(256) gemm_mma(
    const __half* __restrict__ A, const __half* __restrict__ Bmat,
    const float* __restrict__ bias,
    void* o0v, void* o1v, void* o2v, __half* __restrict__ qt)
{
    extern __shared__ char smem[];
    const uint32_t sbase = smem_u32(smem);
    const int tid  = threadIdx.x;
    const int wid  = tid >> 5;
    const int lane = tid & 31;
    const int wm = wid >> 2;
    const int wn = wid & 3;
    const int n0  = blockIdx.x * 128;
    const int Mg0 = blockIdx.y * 128;
    const int b   = blockIdx.z;
    const size_t bB = (size_t)b * HW_;

    const int rowA  = lane & 15;
    const int kbA   = (lane >> 4) * 16;
    const int nrowB = (lane & 7) + (lane >> 4) * 8;
    const int kbB   = ((lane >> 3) & 1) * 16;

    auto load_chunk = [&](int chunk, int buf) {
        const uint32_t Ab = sbase + buf * 32768;
        const uint32_t Bb = Ab + 16384;
        const int kc = chunk * 64;
        #pragma unroll
        for (int it = 0; it < 4; it++) {
            int idx = it * 256 + tid;
            int row = idx >> 3, cb = idx & 7;
            cp16(Ab + sw128((uint32_t)(row * 128 + cb * 16)),
                 A + (size_t)(Mg0 + row) * 512 + kc + cb * 8);
        }
        #pragma unroll
        for (int it = 0; it < 4; it++) {
            int idx = it * 256 + tid;
            int row = idx >> 3, cb = idx & 7;
            cp16(Bb + sw128((uint32_t)(row * 128 + cb * 16)),
                 Bmat + (bB + n0 + row) * 512 + kc + cb * 8);
        }
        cp_commit();
    };

    float acc[4][4][4];
    #pragma unroll
    for (int i = 0; i < 4; i++)
        #pragma unroll
        for (int j = 0; j < 4; j++)
            #pragma unroll
            for (int r = 0; r < 4; r++) acc[i][j][r] = 0.f;

    load_chunk(0, 0);
    load_chunk(1, 1);

    for (int i = 0; i < 8; i++) {
        if (i + 1 < 8) cp_wait<1>();
        else           cp_wait<0>();
        __syncthreads();
        if (i + 2 < 8) load_chunk(i + 2, (i + 2) % 3);

        const uint32_t Ab = sbase + (i % 3) * 32768;
        const uint32_t Bb = Ab + 16384;
        #pragma unroll
        for (int ks = 0; ks < 4; ks++) {
            uint32_t af[4][4];
            #pragma unroll
            for (int mi = 0; mi < 4; mi++) {
                uint32_t off = (uint32_t)((wm * 64 + mi * 16 + rowA) * 128 + ks * 32 + kbA);
                ldsm4(af[mi][0], af[mi][1], af[mi][2], af[mi][3], Ab + sw128(off));
            }
            uint32_t bf[8];
            #pragma unroll
            for (int j = 0; j < 2; j++) {
                uint32_t off = (uint32_t)((wn * 32 + j * 16 + nrowB) * 128 + ks * 32 + kbB);
                ldsm4(bf[j * 4 + 0], bf[j * 4 + 1], bf[j * 4 + 2], bf[j * 4 + 3],
                      Bb + sw128(off));
            }
            #pragma unroll
            for (int mi = 0; mi < 4; mi++)
                #pragma unroll
                for (int ni = 0; ni < 4; ni++)
                    mma16816(acc[mi][ni], af[mi][0], af[mi][1], af[mi][2], af[mi][3],
                             bf[2 * ni], bf[2 * ni + 1]);
        }
    }
    __syncthreads();

    const int sel = blockIdx.y >> 2;

    if (QFUSE && sel == 0) {
        // --- fused channel softmax + transpose for q ---
        float* tile = (float*)smem;   // [128][132]
        #pragma unroll
        for (int mi = 0; mi < 4; mi++) {
            #pragma unroll
            for (int pair = 0; pair < 2; pair++) {
                const int msub = wm * 64 + mi * 16 + (lane >> 2) + pair * 8;
                const float bv = bias[Mg0 + msub];
                #pragma unroll
                for (int ni = 0; ni < 4; ni++) {
                    const int c = wn * 32 + ni * 8 + 2 * (lane & 3);
                    tile[msub * 132 + c]     = acc[mi][ni][pair * 2 + 0] + bv;
                    tile[msub * 132 + c + 1] = acc[mi][ni][pair * 2 + 1] + bv;
                }
            }
        }
        __syncthreads();
        // each thread: one (head, column); softmax over 64 channels
        const int col = tid & 127;
        const int hs  = tid >> 7;                       // 0..1
        const int head = (blockIdx.y & 3) * 2 + hs;
        float r[64];
        float mx = -1e30f;
        #pragma unroll
        for (int k = 0; k < 64; k++) {
            r[k] = tile[(hs * 64 + k) * 132 + col];
            mx = fmaxf(mx, r[k]);
        }
        float s = 0.f;
        #pragma unroll
        for (int k = 0; k < 64; k++) { r[k] = expf(r[k] - mx); s += r[k]; }
        const float inv = 1.0f / s;
        __half2 h2[32];
        #pragma unroll
        for (int k = 0; k < 32; k++)
            h2[k] = __floats2half2_rn(r[2 * k] * inv, r[2 * k + 1] * inv);
        uint4* dst = (uint4*)(qt + ((size_t)(b * 8 + head) * HW_ + n0 + col) * 64);
        uint4* srcp = (uint4*)h2;
        #pragma unroll
        for (int i = 0; i < 8; i++) dst[i] = srcp[i];
        return;
    }

    const int mloc_cta = (blockIdx.y & 3) * 128;
    const int ncta0 = n0 + wn * 32 + 2 * (lane & 3);
    #pragma unroll
    for (int mi = 0; mi < 4; mi++) {
        #pragma unroll
        for (int pair = 0; pair < 2; pair++) {
            const int msub = wm * 64 + mi * 16 + (lane >> 2) + pair * 8;
            const int mloc = mloc_cta + msub;
            const float bv = bias[Mg0 + msub];
            if (OUT_HALF) {
                __half* outp = (__half*)((sel == 0) ? o0v : (sel == 1) ? o1v : o2v);
                __half* rowp = outp + ((size_t)b * 512 + mloc) * HW_;
                #pragma unroll
                for (int ni = 0; ni < 4; ni++) {
                    __half2 v = __floats2half2_rn(acc[mi][ni][pair * 2 + 0] + bv,
                                                  acc[mi][ni][pair * 2 + 1] + bv);
                    *(__half2*)(rowp + ncta0 + ni * 8) = v;
                }
            } else {
                float* outp = (float*)((sel == 0) ? o0v : (sel == 1) ? o1v : o2v);
                float* rowp = outp + ((size_t)b * 512 + mloc) * HW_;
                #pragma unroll
                for (int ni = 0; ni < 4; ni++) {
                    float2 v;
                    v.x = acc[mi][ni][pair * 2 + 0] + bv;
                    v.y = acc[mi][ni][pair * 2 + 1] + bv;
                    *(float2*)(rowp + ncta0 + ni * 8) = v;
                }
            }
        }
    }
}

// ------------------------- softmax over spatial axis, fp16 in/out -------------------------
__global__ void __launch_bounds__(256) softmax_spatial_h(__half* __restrict__ data)
{
    __shared__ float buf[HW_];
    __shared__ float red[8];
    __shared__ float bcast;
    __half2* p2 = (__half2*)(data + (size_t)blockIdx.x * HW_);
    const int tid = threadIdx.x;

    float mx = -1e30f;
    #pragma unroll
    for (int r = 0; r < 8; r++) {
        int idx = tid + r * 256;
        float2 f = __half22float2(p2[idx]);
        buf[2 * idx] = f.x; buf[2 * idx + 1] = f.y;
        mx = fmaxf(mx, fmaxf(f.x, f.y));
    }
    #pragma unroll
    for (int o = 16; o > 0; o >>= 1) mx = fmaxf(mx, __shfl_xor_sync(~0u, mx, o));
    if ((tid & 31) == 0) red[tid >> 5] = mx;
    __syncthreads();
    if (tid == 0) {
        float m = red[0];
        #pragma unroll
        for (int i = 1; i < 8; i++) m = fmaxf(m, red[i]);
        bcast = m;
    }
    __syncthreads();
    mx = bcast;

    float s = 0.f;
    #pragma unroll
    for (int r = 0; r < 8; r++) {
        int idx = tid + r * 256;
        float a = expf(buf[2 * idx] - mx);
        float bvv = expf(buf[2 * idx + 1] - mx);
        buf[2 * idx] = a; buf[2 * idx + 1] = bvv;
        s += a + bvv;
    }
    #pragma unroll
    for (int o = 16; o > 0; o >>= 1) s += __shfl_xor_sync(~0u, s, o);
    if ((tid & 31) == 0) red[tid >> 5] = s;
    __syncthreads();
    if (tid == 0) {
        float m = 0.f;
        #pragma unroll
        for (int i = 0; i < 8; i++) m += red[i];
        bcast = 1.0f / m;
    }
    __syncthreads();
    const float inv = bcast;
    #pragma unroll
    for (int r = 0; r < 8; r++) {
        int idx = tid + r * 256;
        p2[idx] = __floats2half2_rn(buf[2 * idx] * inv, buf[2 * idx + 1] * inv);
    }
}

// ------------------------- ctx HMMA split-K: ctxf[bh][k][v] += sum_l K V -------------------------
#define CTX_SMEM 32768
#define CTX_SPLIT 4
__global__ void __launch_bounds__(256) ctx_mma_split(
    const __half* __restrict__ K, const __half* __restrict__ V,
    float* __restrict__ Ctxf)
{
    extern __shared__ char smem[];
    const uint32_t sbase = smem_u32(smem);
    const int bh = blockIdx.x;
    const int sp = blockIdx.y;
    const int tid = threadIdx.x;
    const int wid = tid >> 5;
    const int lane = tid & 31;
    const int wm = wid >> 1;
    const int wn = wid & 1;
    const __half* Kp = K + (size_t)bh * HK_ * HW_;
    const __half* Vp = V + (size_t)bh * HK_ * HW_;

    const int rowA  = lane & 15;
    const int kbA   = (lane >> 4) * 16;
    const int nrowB = (lane & 7) + (lane >> 4) * 8;
    const int kbB   = ((lane >> 3) & 1) * 16;

    const int c0 = sp * 16;   // chunks of 64 l-positions

    auto load_chunk = [&](int chunk, int buf) {
        const uint32_t Ab = sbase + buf * 16384;
        const uint32_t Bb = Ab + 8192;
        const int lc = chunk * 64;
        #pragma unroll
        for (int it = 0; it < 2; it++) {
            int idx = it * 256 + tid;
            int row = idx >> 3, cb = idx & 7;
            cp16(Ab + sw128((uint32_t)(row * 128 + cb * 16)),
                 Kp + (size_t)row * HW_ + lc + cb * 8);
            cp16(Bb + sw128((uint32_t)(row * 128 + cb * 16)),
                 Vp + (size_t)row * HW_ + lc + cb * 8);
        }
        cp_commit();
    };

    float acc[4][4];
    #pragma unroll
    for (int i = 0; i < 4; i++)
        #pragma unroll
        for (int r = 0; r < 4; r++) acc[i][r] = 0.f;

    load_chunk(c0, 0);
    for (int i = 0; i < 16; i++) {
        if (i + 1 < 16) { load_chunk(c0 + i + 1, (i + 1) & 1); cp_wait<1>(); }
        else             cp_wait<0>();
        __syncthreads();
        const uint32_t Ab = sbase + (i & 1) * 16384;
        const uint32_t Bb = Ab + 8192;
        #pragma unroll
        for (int ks = 0; ks < 4; ks++) {
            uint32_t a0, a1, a2, a3;
            ldsm4(a0, a1, a2, a3,
                  Ab + sw128((uint32_t)((wm * 16 + rowA) * 128 + ks * 32 + kbA)));
            uint32_t bf[8];
            #pragma unroll
            for (int j = 0; j < 2; j++)
                ldsm4(bf[j * 4 + 0], bf[j * 4 + 1], bf[j * 4 + 2], bf[j * 4 + 3],
                      Bb + sw128((uint32_t)((wn * 32 + j * 16 + nrowB) * 128 + ks * 32 + kbB)));
            #pragma unroll
            for (int ni = 0; ni < 4; ni++)
                mma16816(acc[ni], a0, a1, a2, a3, bf[2 * ni], bf[2 * ni + 1]);
        }
        __syncthreads();
    }

    float* dst = Ctxf + (size_t)bh * 4096;
    const int r0 = wm * 16 + (lane >> 2);
    #pragma unroll
    for (int ni = 0; ni < 4; ni++) {
        const int col = wn * 32 + ni * 8 + 2 * (lane & 3);
        atomicAdd(dst + r0 * 64 + col,           acc[ni][0]);
        atomicAdd(dst + r0 * 64 + col + 1,       acc[ni][1]);
        atomicAdd(dst + (r0 + 8) * 64 + col,     acc[ni][2]);
        atomicAdd(dst + (r0 + 8) * 64 + col + 1, acc[ni][3]);
    }
}

// ------------------------- ctx convert: fp32 [k][v] -> fp16 transposed [v][k] -------------------------
__global__ void __launch_bounds__(256) ctx_cvt(
    const float* __restrict__ Ctxf, __half* __restrict__ CtxT)
{
    const int bh = blockIdx.x;
    const int tid = threadIdx.x;
    const int v  = tid >> 2;
    const int k0 = (tid & 3) * 16;
    const float* src = Ctxf + (size_t)bh * 4096;
    __half* dst = CtxT + (size_t)bh * 4096 + v * 64 + k0;
    #pragma unroll
    for (int j = 0; j < 8; j++) {
        *(__half2*)(dst + 2 * j) =
            __floats2half2_rn(src[(k0 + 2 * j) * 64 + v],
                              src[(k0 + 2 * j + 1) * 64 + v]);
    }
}

// ------------------------- av HMMA: AVt[b][l][h*64+v] = sum_k ctxT[v,k] qt[l,k] -------------------------
#define AV_SMEM (8192 + 32768)
__global__ void __launch_bounds__(256) av_mma(
    const __half* __restrict__ CtxT, const __half* __restrict__ Qt,
    __half* __restrict__ AVt)
{
    extern __shared__ char smem[];
    const uint32_t sbase = smem_u32(smem);
    const int bh = blockIdx.y;
    const int l0 = blockIdx.x * 256;
    const int tid = threadIdx.x;
    const int wid = tid >> 5;
    const int lane = tid & 31;
    const int wm = wid >> 2;
    const int wn = wid & 3;

    const int rowA  = lane & 15;
    const int kbA   = (lane >> 4) * 16;
    const int nrowB = (lane & 7) + (lane >> 4) * 8;
    const int kbB   = ((lane >> 3) & 1) * 16;

    const uint32_t Ab = sbase;
    const uint32_t Bb = sbase + 8192;

    #pragma unroll
    for (int it = 0; it < 2; it++) {
        int idx = it * 256 + tid;
        int row = idx >> 3, cb = idx & 7;
        cp16(Ab + sw128((uint32_t)(row * 128 + cb * 16)),
             CtxT + (size_t)bh * 4096 + row * 64 + cb * 8);
    }
    #pragma unroll
    for (int it = 0; it < 8; it++) {
        int idx = it * 256 + tid;
        int row = idx >> 3, cb = idx & 7;
        cp16(Bb + sw128((uint32_t)(row * 128 + cb * 16)),
             Qt + ((size_t)bh * HW_ + l0 + row) * 64 + cb * 8);
    }
    cp_commit();
    cp_wait<0>();
    __syncthreads();

    float acc[2][8][4];
    #pragma unroll
    for (int i = 0; i < 2; i++)
        #pragma unroll
        for (int j = 0; j < 8; j++)
            #pragma unroll
            for (int r = 0; r < 4; r++) acc[i][j][r] = 0.f;

    #pragma unroll
    for (int ks = 0; ks < 4; ks++) {
        uint32_t af[2][4];
        #pragma unroll
        for (int mi = 0; mi < 2; mi++)
            ldsm4(af[mi][0], af[mi][1], af[mi][2], af[mi][3],
                  Ab + sw128((uint32_t)((wm * 32 + mi * 16 + rowA) * 128 + ks * 32 + kbA)));
        uint32_t bf[4][4];
        #pragma unroll
        for (int j = 0; j < 4; j++)
            ldsm4(bf[j][0], bf[j][1], bf[j][2], bf[j][3],
                  Bb + sw128((uint32_t)((wn * 64 + j * 16 + nrowB) * 128 + ks * 32 + kbB)));
        #pragma unroll
        for (int mi = 0; mi < 2; mi++)
            #pragma unroll
            for (int ni = 0; ni < 8; ni++) {
                int j = ni >> 1, pr = (ni & 1) * 2;
                mma16816(acc[mi][ni], af[mi][0], af[mi][1], af[mi][2], af[mi][3],
                         bf[j][pr], bf[j][pr + 1]);
            }
    }
    __syncthreads();

    __half* outs = (__half*)(smem + 8192);   // [256][64]
    #pragma unroll
    for (int mi = 0; mi < 2; mi++) {
        const int r0 = wm * 32 + mi * 16 + (lane >> 2);
        #pragma unroll
        for (int ni = 0; ni < 8; ni++) {
            const int n = wn * 64 + ni * 8 + 2 * (lane & 3);
            outs[n * 64 + r0]           = __float2half(acc[mi][ni][0]);
            outs[(n + 1) * 64 + r0]     = __float2half(acc[mi][ni][1]);
            outs[n * 64 + r0 + 8]       = __float2half(acc[mi][ni][2]);
            outs[(n + 1) * 64 + r0 + 8] = __float2half(acc[mi][ni][3]);
        }
    }
    __syncthreads();

    const int b = bh >> 3;
    const int h = bh & 7;
    const __half2* src2 = (const __half2*)outs;
    #pragma unroll
    for (int it = 0; it < 32; it++) {
        int idx = it * 256 + tid;
        int row = idx >> 5;
        int c2  = idx & 31;
        *(__half2*)(AVt + ((size_t)b * HW_ + l0 + row) * 512 + h * 64 + c2 * 2) = src2[idx];
    }
}

// ---------------------------------------------------------------------------
extern "C" void kernel_launch(void* const* d_in, const int* in_sizes, int n_in,
                              void* d_out, int out_size)
{
    const float* x  = (const float*)d_in[0];
    const float* Wk = (const float*)d_in[1];
    const float* bk = (const float*)d_in[2];
    const float* Wq = (const float*)d_in[3];
    const float* bq = (const float*)d_in[4];
    const float* Wv = (const float*)d_in[5];
    const float* bv = (const float*)d_in[6];
    const float* Wr = (const float*)d_in[7];
    const float* br = (const float*)d_in[8];
    float* out = (float*)d_out;

    float *bcat, *ctxf;
    __half *xt, *kh, *vh, *qt, *ctxh, *wc, *wr;
    cudaGetSymbolAddress((void**)&bcat, g_bcat);
    cudaGetSymbolAddress((void**)&xt,   g_xt);
    cudaGetSymbolAddress((void**)&kh,   g_kh);
    cudaGetSymbolAddress((void**)&vh,   g_vh);
    cudaGetSymbolAddress((void**)&qt,   g_qt);
    cudaGetSymbolAddress((void**)&ctxf, g_ctxf);
    cudaGetSymbolAddress((void**)&ctxh, g_ctxh);
    cudaGetSymbolAddress((void**)&wc,   g_wc);
    cudaGetSymbolAddress((void**)&wr,   g_wr);

    cudaFuncSetAttribute(gemm_mma<true, true>,
                         cudaFuncAttributeMaxDynamicSharedMemorySize, GEMM_SMEM_TOTAL);
    cudaFuncSetAttribute(gemm_mma<false, false>,
                         cudaFuncAttributeMaxDynamicSharedMemorySize, GEMM_SMEM_TOTAL);

    weight_prep<<<4096, 256>>>(Wq, bq, Wk, bk, Wv, bv, Wr);
    transpose_cvt<<<dim3(HW_ / 32, C_ / 32, B_), dim3(32, 8)>>>(x);
    cudaMemsetAsync(ctxf, 0, (size_t)B_ * HEADS_ * HK_ * HK_ * sizeof(float));

    // QKV projection: q -> fused softmax+transpose into qt; k,v -> fp16
    gemm_mma<true, true><<<dim3(32, 12, B_), 256, GEMM_SMEM_TOTAL>>>(
        wc, xt, bcat, nullptr, kh, vh, qt);

    softmax_spatial_h<<<B_ * C_, 256>>>(kh);

    ctx_mma_split<<<dim3(B_ * HEADS_, CTX_SPLIT), 256, CTX_SMEM>>>(kh, vh, ctxf);
    ctx_cvt<<<B_ * HEADS_, 256>>>(ctxf, ctxh);
    av_mma<<<dim3(HW_ / 256, B_ * HEADS_), 256, AV_SMEM>>>(ctxh, qt, xt);  // AVt into g_xt

    // output projection: fp32 out
    gemm_mma<false, false><<<dim3(32, 4, B_), 256, GEMM_SMEM_TOTAL>>>(
        wr, xt, br, out, out, out, nullptr);
}